// round 8
// baseline (speedup 1.0000x reference)
#include <cuda_runtime.h>
#include <cuda_bf16.h>
#include <cstdint>

#define DD 512
#define MAXN 200000
#define TAU_INV 2.0f
#define EPS 1e-8f

// ---------------- device scratch (no allocations allowed) ----------------
__device__ __align__(256) __nv_bfloat16 g_zbf[(size_t)MAXN * DD];  // z bf16
__device__ __align__(256) __nv_bfloat16 g_wbf[DD * DD];            // W bf16
__device__ float g_s[MAXN];                          // row sumsq of z
__device__ float g_d2[MAXN];
__device__ float g_dot[MAXN];                        // z . v
__device__ float g_nsq[MAXN];                        // ||x_proj||^2
__device__ float g_colsum[DD];
__device__ float g_c0[DD];
__device__ float g_cp[DD];                           // unnormalized centroid
__device__ float g_c[DD];                            // centroid
__device__ float g_v[DD];                            // v = W^T c (fp32)
__device__ float g_cc;                               // ||c0||^2
__device__ float g_Z;
__device__ float g_bc;                               // b . c
__device__ float g_cnorm;
__device__ int   g_d2min_bits;

// ---------------- streams/events for parallel graph branches -------------
static cudaStream_t g_s1;
static cudaEvent_t g_ev0, g_evZ, g_ev1;
static struct StreamInit {
    StreamInit() {
        cudaStreamCreateWithFlags(&g_s1, cudaStreamNonBlocking);
        cudaEventCreateWithFlags(&g_ev0, cudaEventDisableTiming);
        cudaEventCreateWithFlags(&g_evZ, cudaEventDisableTiming);
        cudaEventCreateWithFlags(&g_ev1, cudaEventDisableTiming);
    }
} g_stream_init;

// ---------------- helpers ----------------
__device__ __forceinline__ uint32_t smem_u32(const void* p) {
    return (uint32_t)__cvta_generic_to_shared(p);
}
__device__ __forceinline__ void ldmx4(uint32_t* r, uint32_t addr) {
    asm volatile("ldmatrix.sync.aligned.m8n8.x4.shared.b16 {%0,%1,%2,%3}, [%4];"
                 : "=r"(r[0]), "=r"(r[1]), "=r"(r[2]), "=r"(r[3]) : "r"(addr));
}
__device__ __forceinline__ void mma16816(float* c, const uint32_t* a, const uint32_t* b) {
    asm volatile("mma.sync.aligned.m16n8k16.row.col.f32.bf16.bf16.f32 "
                 "{%0,%1,%2,%3}, {%4,%5,%6,%7}, {%8,%9}, {%0,%1,%2,%3};"
                 : "+f"(c[0]), "+f"(c[1]), "+f"(c[2]), "+f"(c[3])
                 : "r"(a[0]), "r"(a[1]), "r"(a[2]), "r"(a[3]), "r"(b[0]), "r"(b[1]));
}
__device__ __forceinline__ void cp_async16(uint32_t sdst, const void* gsrc) {
    asm volatile("cp.async.cg.shared.global [%0], [%1], 16;"
                 :: "r"(sdst), "l"(gsrc) : "memory");
}
__device__ __forceinline__ void cp_commit() {
    asm volatile("cp.async.commit_group;" ::: "memory");
}
__device__ __forceinline__ void cp_wait1() {
    asm volatile("cp.async.wait_group 1;" ::: "memory");
}

// ================= k0a: zero accumulators =================
__global__ void k0a_zero() {
    int i = blockIdx.x * blockDim.x + threadIdx.x;
    if (i < DD) { g_colsum[i] = 0.f; g_cp[i] = 0.f; g_v[i] = 0.f; }
    if (i == DD) g_Z = 0.f;
    if (i == DD + 1) g_d2min_bits = 0x7f7fffff;
}

// ================= k0b: W -> bf16 (side stream) =================
__global__ void k0b_wcvt(const float* __restrict__ W) {
    int i = blockIdx.x * blockDim.x + threadIdx.x;
    int stride = gridDim.x * blockDim.x;
    for (int j = i; j < DD * DD; j += stride) g_wbf[j] = __float2bfloat16(W[j]);
}

// ================= k1: colsums + row sumsq + z->bf16 =================
__global__ void k1_pass1(const float* __restrict__ z, int N) {
    __shared__ float scol[DD];
    const int tid = threadIdx.x, wid = tid >> 5, lane = tid & 31;
    for (int i = tid; i < DD; i += blockDim.x) scol[i] = 0.f;
    __syncthreads();
    const int gw = blockIdx.x * (blockDim.x >> 5) + wid;
    const int nw = gridDim.x * (blockDim.x >> 5);
    float cs[16];
#pragma unroll
    for (int i = 0; i < 16; i++) cs[i] = 0.f;
    for (int row = gw; row < N; row += nw) {
        const float4* zr = (const float4*)(z + (size_t)row * DD);
        float ssq = 0.f;
#pragma unroll
        for (int c = 0; c < 4; c++) {
            float4 v = __ldcs(zr + c * 32 + lane);
            ssq += v.x * v.x + v.y * v.y + v.z * v.z + v.w * v.w;
            cs[c * 4 + 0] += v.x; cs[c * 4 + 1] += v.y;
            cs[c * 4 + 2] += v.z; cs[c * 4 + 3] += v.w;
            __nv_bfloat162 b0 = __floats2bfloat162_rn(v.x, v.y);
            __nv_bfloat162 b1 = __floats2bfloat162_rn(v.z, v.w);
            float2 u;
            u.x = __uint_as_float(*reinterpret_cast<uint32_t*>(&b0));
            u.y = __uint_as_float(*reinterpret_cast<uint32_t*>(&b1));
            __stcs((float2*)(g_zbf + (size_t)row * DD + c * 128 + lane * 4), u);
        }
#pragma unroll
        for (int o = 16; o > 0; o >>= 1) ssq += __shfl_xor_sync(0xffffffffu, ssq, o);
        if (lane == 0) g_s[row] = ssq;
    }
#pragma unroll
    for (int c = 0; c < 4; c++)
#pragma unroll
        for (int e = 0; e < 4; e++)
            atomicAdd(&scol[c * 128 + lane * 4 + e], cs[c * 4 + e]);
    __syncthreads();
    for (int i = tid; i < DD; i += blockDim.x) atomicAdd(&g_colsum[i], scol[i]);
}

// ================= k2: c0 = colsum/N, cc = ||c0||^2 =================
__global__ void k2_c0(int N) {
    __shared__ float red[16];
    const int tid = threadIdx.x; // 512
    float c0 = g_colsum[tid] / (float)N;
    g_c0[tid] = c0;
    float sq = c0 * c0;
#pragma unroll
    for (int o = 16; o > 0; o >>= 1) sq += __shfl_xor_sync(0xffffffffu, sq, o);
    if ((tid & 31) == 0) red[tid >> 5] = sq;
    __syncthreads();
    if (tid < 16) {
        float s = red[tid];
#pragma unroll
        for (int o = 8; o > 0; o >>= 1) s += __shfl_xor_sync(0xffffu, s, o);
        if (tid == 0) g_cc = s;
    }
}

// ================= k3: d2 = s - 2 h.c0 + cc (bf16 h), block-min ==========
__global__ void k3_d2(int N) {
    __shared__ __align__(16) float c0s[DD];
    __shared__ int smin;
    const int tid = threadIdx.x, wid = tid >> 5, lane = tid & 31;
    for (int i = tid; i < DD; i += blockDim.x) c0s[i] = g_c0[i];
    if (tid == 0) smin = 0x7f7fffff;
    __syncthreads();
    const float cc = g_cc;
    const int gw = blockIdx.x * (blockDim.x >> 5) + wid;
    const int nw = gridDim.x * (blockDim.x >> 5);
    for (int r4 = gw * 4; r4 < N; r4 += nw * 4) {
        float t[4] = {0.f, 0.f, 0.f, 0.f};
        int nr = (N - r4 < 4) ? (N - r4) : 4;
#pragma unroll
        for (int q = 0; q < 4; q++) {
            int row = r4 + ((q < nr) ? q : 0);
#pragma unroll
            for (int c = 0; c < 2; c++) {
                uint4 u = __ldcs((const uint4*)(g_zbf + (size_t)row * DD + c * 256 + lane * 8));
                const __nv_bfloat162* p = (const __nv_bfloat162*)&u;
                float4 cv0 = ((const float4*)c0s)[c * 64 + lane * 2];
                float4 cv1 = ((const float4*)c0s)[c * 64 + lane * 2 + 1];
                float2 f0 = __bfloat1622float2(p[0]);
                float2 f1 = __bfloat1622float2(p[1]);
                float2 f2 = __bfloat1622float2(p[2]);
                float2 f3 = __bfloat1622float2(p[3]);
                t[q] += f0.x * cv0.x + f0.y * cv0.y + f1.x * cv0.z + f1.y * cv0.w
                      + f2.x * cv1.x + f2.y * cv1.y + f3.x * cv1.z + f3.y * cv1.w;
            }
        }
#pragma unroll
        for (int q = 0; q < 4; q++)
#pragma unroll
            for (int o = 16; o > 0; o >>= 1)
                t[q] += __shfl_xor_sync(0xffffffffu, t[q], o);
        if (lane == 0) {
            int lmin = 0x7f7fffff;
#pragma unroll
            for (int q = 0; q < 4; q++) {
                if (q < nr) {
                    float d2 = g_s[r4 + q] - 2.f * t[q] + cc;
                    g_d2[r4 + q] = d2;
                    int bits = __float_as_int(d2);
                    if (bits < lmin) lmin = bits;
                }
            }
            atomicMin(&smin, lmin);
        }
    }
    __syncthreads();
    if (tid == 0) atomicMin(&g_d2min_bits, smin);
}

// ================= k45: Z + unnormalized centroid c' =====================
__global__ void k45_Zc(const float* __restrict__ z, int N) {
    __shared__ float red[8];
    const int tid = threadIdx.x, lane = tid & 31;
    const float d2min = __int_as_float(g_d2min_bits);
    const int gidx = blockIdx.x * blockDim.x + tid;
    const int stride = gridDim.x * blockDim.x;
    const int numIter = (N + stride - 1) / stride;
    float zpart = 0.f;
    for (int i = 0; i < numIter; i++) {
        int r = gidx + i * stride;
        float e = 0.f;
        if (r < N) e = __expf((d2min - g_d2[r]) * TAU_INV);
        zpart += e;
        unsigned mask = __ballot_sync(0xffffffffu, e > 1e-13f);
        while (mask) {
            int src = __ffs(mask) - 1;
            mask &= mask - 1;
            int rb = __shfl_sync(0xffffffffu, r, src);
            float eb = __shfl_sync(0xffffffffu, e, src);
            const float* zr = z + (size_t)rb * DD;
#pragma unroll
            for (int c = 0; c < 16; c++)
                atomicAdd(&g_cp[c * 32 + lane], eb * zr[c * 32 + lane]);
        }
    }
#pragma unroll
    for (int o = 16; o > 0; o >>= 1) zpart += __shfl_xor_sync(0xffffffffu, zpart, o);
    if (lane == 0) red[tid >> 5] = zpart;
    __syncthreads();
    if (tid < 8) {
        float t = red[tid];
#pragma unroll
        for (int o = 4; o > 0; o >>= 1) t += __shfl_xor_sync(0xffu, t, o);
        if (tid == 0) atomicAdd(&g_Z, t);
    }
}

// ================= k7: c = c'/Z, cnorm, bc =================
__global__ void k7_norm(const float* __restrict__ b) {
    __shared__ float redc[16], redb[16];
    const int tid = threadIdx.x; // 512
    const float invZ = 1.f / g_Z;
    float cv = g_cp[tid] * invZ;
    g_c[tid] = cv;
    float pc = cv * cv;
    float pb = cv * b[tid];
#pragma unroll
    for (int o = 16; o > 0; o >>= 1) {
        pc += __shfl_xor_sync(0xffffffffu, pc, o);
        pb += __shfl_xor_sync(0xffffffffu, pb, o);
    }
    if ((tid & 31) == 0) { redc[tid >> 5] = pc; redb[tid >> 5] = pb; }
    __syncthreads();
    if (tid < 16) {
        float sc = redc[tid], sb = redb[tid];
#pragma unroll
        for (int o = 8; o > 0; o >>= 1) {
            sc += __shfl_xor_sync(0xffffu, sc, o);
            sb += __shfl_xor_sync(0xffffu, sb, o);
        }
        if (tid == 0) { g_cnorm = fmaxf(sqrtf(sc), EPS); g_bc = sb; }
    }
}

// ================= k6: v = W^T c (fp32 exact) =================
__global__ void k6_v(const float* __restrict__ W) {
    __shared__ float cs[16];
    const int tid = threadIdx.x; // 512
    const int j0 = blockIdx.x * 16;
    if (tid < 16) cs[tid] = g_c[j0 + tid];
    __syncthreads();
    float acc = 0.f;
#pragma unroll
    for (int jj = 0; jj < 16; jj++)
        acc += cs[jj] * W[(size_t)(j0 + jj) * DD + tid];
    atomicAdd(&g_v[tid], acc);
}

// ================= k9: dot_i = z_i . v (bf16 z) =================
__global__ void k9_dot(int N) {
    __shared__ __align__(16) float sv[DD];
    const int tid = threadIdx.x, wid = tid >> 5, lane = tid & 31;
    for (int i = tid; i < DD; i += blockDim.x) sv[i] = g_v[i];
    __syncthreads();
    const int gw = blockIdx.x * (blockDim.x >> 5) + wid;
    const int nw = gridDim.x * (blockDim.x >> 5);
    for (int row = gw; row < N; row += nw) {
        float d = 0.f;
#pragma unroll
        for (int c = 0; c < 2; c++) {
            uint4 u = __ldcs((const uint4*)(g_zbf + (size_t)row * DD + c * 256 + lane * 8));
            const __nv_bfloat162* p = (const __nv_bfloat162*)&u;
            float4 v0 = ((const float4*)sv)[c * 64 + lane * 2];
            float4 v1 = ((const float4*)sv)[c * 64 + lane * 2 + 1];
            float2 f0 = __bfloat1622float2(p[0]);
            float2 f1 = __bfloat1622float2(p[1]);
            float2 f2 = __bfloat1622float2(p[2]);
            float2 f3 = __bfloat1622float2(p[3]);
            d += f0.x * v0.x + f0.y * v0.y + f1.x * v0.z + f1.y * v0.w
               + f2.x * v1.x + f2.y * v1.y + f3.x * v1.z + f3.y * v1.w;
        }
#pragma unroll
        for (int o = 16; o > 0; o >>= 1) d += __shfl_xor_sync(0xffffffffu, d, o);
        if (lane == 0) g_dot[row] = d;
    }
}

// ================= k8: bf16 mma GEMM, 512 threads / 16 warps ==============
// 4 m-groups x 4 j-groups of m32 x j32 -> m128 x j128 per iteration.
// j-chunk 128, k-chunk 128 (32 KB buf) double-buffered. A resident 128 KB.
#define K8_A    0
#define K8_B    131072
#define K8_BB   32768
#define K8_BV   196608
#define K8_NSQ  198656
#define K8_SMEM 199680

__global__ void __launch_bounds__(512, 1)
k8_gemm(const float* __restrict__ b_in, int N) {
    extern __shared__ char smem[];
    const uint32_t sbase = smem_u32(smem);
    const int tid = threadIdx.x, warp = tid >> 5, lane = tid & 31;
    const int m0 = blockIdx.x * 128;

    float* sbv = (float*)(smem + K8_BV);
    float* snq = (float*)(smem + K8_NSQ);
    for (int i = tid; i < DD; i += 512) sbv[i] = b_in[i];
    if (tid < 128) snq[tid] = 0.f;

    // ---- prefetch B buffers 0 and 1 (j128 x k128, pitch 256B) ----
#pragma unroll 1
    for (int h = 0; h < 2; h++) {
        const uint32_t bbuf = sbase + K8_B + (h & 1) * K8_BB;
        const int jc = h >> 2, kh = h & 3;
#pragma unroll
        for (int it = 0; it < 4; it++) {
            int idx = it * 512 + tid;
            int j = idx >> 4, ci = idx & 15;
            cp_async16(bbuf + j * 256 + ((ci ^ (j & 7)) << 4),
                       g_wbf + (size_t)(jc * 128 + j) * DD + kh * 128 + ci * 8);
        }
        cp_commit();
    }

    // ---- load A: 128 rows x 512 bf16, pitch 1024, XOR swizzle ----
#pragma unroll
    for (int it = 0; it < 16; it++) {
        int idx = it * 512 + tid;
        int r = idx >> 6, ci = idx & 63;
        int grow = m0 + r; if (grow > N - 1) grow = N - 1;
        uint4 val = *(const uint4*)(g_zbf + (size_t)grow * DD + ci * 8);
        *(uint4*)(smem + K8_A + r * 1024 + ((ci ^ (r & 7)) << 4)) = val;
    }

    // ---- warp coords: mg = warp&3 (m32), jg = warp>>2 (j32 of j128) ----
    const int mg = warp & 3, jg = warp >> 2;
    const int mbase = mg * 32;
    const uint32_t swa = lane & 7;
    const uint32_t a0base = sbase + K8_A + (uint32_t)(mbase + (lane & 15)) * 1024;
    const int jrow = (lane & 7) + ((lane >> 4) << 3);
    const uint32_t brow_off = (uint32_t)(jg * 32 + jrow) * 256;
    const uint32_t ciBofs = (lane >> 3) & 1;
    const uint32_t ciAofs = lane >> 4;

    float acc[8][4];
#pragma unroll
    for (int t = 0; t < 8; t++)
#pragma unroll
        for (int e = 0; e < 4; e++) acc[t][e] = 0.f;
    float nsq[2][2] = {{0.f, 0.f}, {0.f, 0.f}};

    for (int h = 0; h < 16; h++) {           // jc = h>>2 (j128), kh = h&3 (k128)
        const int buf = h & 1, jc = h >> 2, kh = h & 3;
        cp_wait1();
        __syncthreads();
        const uint32_t b0base = sbase + K8_B + buf * K8_BB + brow_off;

#pragma unroll
        for (int ktl = 0; ktl < 8; ktl++) {  // k16 steps within k128
            uint32_t a0[4], a1[4], b0[4], b1[4];
            uint32_t ciA = (uint32_t)(kh * 8 + ktl) * 2 + ciAofs;
            uint32_t adr = a0base + ((ciA ^ swa) << 4);
            ldmx4(a0, adr);
            ldmx4(a1, adr + 16 * 1024);
            uint32_t ciB = (uint32_t)ktl * 2 + ciBofs;
            uint32_t bdr = b0base + ((ciB ^ swa) << 4);
            ldmx4(b0, bdr);
            ldmx4(b1, bdr + 16 * 256);
            mma16816(acc[0], a0, b0 + 0);
            mma16816(acc[1], a0, b0 + 2);
            mma16816(acc[2], a0, b1 + 0);
            mma16816(acc[3], a0, b1 + 2);
            mma16816(acc[4], a1, b0 + 0);
            mma16816(acc[5], a1, b0 + 2);
            mma16816(acc[6], a1, b1 + 0);
            mma16816(acc[7], a1, b1 + 2);
        }
        __syncthreads();   // all warps done with buf before refill

        if (kh == 3) {
            // j128 chunk complete over full k512: fold (acc + b)^2, reset acc
#pragma unroll
            for (int mt = 0; mt < 2; mt++)
#pragma unroll
                for (int nt = 0; nt < 4; nt++) {
                    int jglob = jc * 128 + jg * 32 + nt * 8 + (lane & 3) * 2;
                    float bx = sbv[jglob], by = sbv[jglob + 1];
                    float* a = acc[mt * 4 + nt];
                    float v0 = a[0] + bx, v1 = a[1] + by;
                    float v2 = a[2] + bx, v3 = a[3] + by;
                    nsq[mt][0] += v0 * v0 + v1 * v1;
                    nsq[mt][1] += v2 * v2 + v3 * v3;
                    a[0] = 0.f; a[1] = 0.f; a[2] = 0.f; a[3] = 0.f;
                }
        }
        if (h + 2 < 16) {
            const int h2 = h + 2;
            const uint32_t bbuf = sbase + K8_B + buf * K8_BB;
            const int jc2 = h2 >> 2, kh2 = h2 & 3;
#pragma unroll
            for (int it = 0; it < 4; it++) {
                int idx = it * 512 + tid;
                int j = idx >> 4, ci = idx & 15;
                cp_async16(bbuf + j * 256 + ((ci ^ (j & 7)) << 4),
                           g_wbf + (size_t)(jc2 * 128 + j) * DD + kh2 * 128 + ci * 8);
            }
        }
        cp_commit();
    }

    // ---- merge lane partials: quad lanes share a row; 4 j-groups merge ----
#pragma unroll
    for (int mt = 0; mt < 2; mt++)
#pragma unroll
        for (int hh = 0; hh < 2; hh++) {
            float vn = nsq[mt][hh];
            vn += __shfl_xor_sync(0xffffffffu, vn, 1);
            vn += __shfl_xor_sync(0xffffffffu, vn, 2);
            if ((lane & 3) == 0)
                atomicAdd(&snq[mbase + mt * 16 + hh * 8 + (lane >> 2)], vn);
        }
    __syncthreads();

    if (tid < 128 && m0 + tid < N) g_nsq[m0 + tid] = snq[tid];
}

// ================= k10: finalize dist =================
__global__ void k10_final(float* __restrict__ out, int N) {
    int i = blockIdx.x * blockDim.x + threadIdx.x;
    if (i < N) {
        float nx = fmaxf(sqrtf(g_nsq[i]), EPS);
        out[i] = 1.0f - (g_dot[i] + g_bc) / (nx * g_cnorm);
    }
}

// ================= launch (forked graph) =================
extern "C" void kernel_launch(void* const* d_in, const int* in_sizes, int n_in,
                              void* d_out, int out_size) {
    const float* z = (const float*)d_in[0];
    const float* W = (const float*)d_in[1];
    const float* b = (const float*)d_in[2];
    float* out = (float*)d_out;
    const int N = in_sizes[0] / DD;

    cudaEventRecord(g_ev0, 0);
    cudaStreamWaitEvent(g_s1, g_ev0, 0);

    k0b_wcvt<<<512, 256, 0, g_s1>>>(W);

    k0a_zero<<<3, 256>>>();
    k1_pass1<<<1184, 256>>>(z, N);

    cudaEventRecord(g_evZ, 0);
    cudaStreamWaitEvent(g_s1, g_evZ, 0);
    cudaFuncSetAttribute(k8_gemm, cudaFuncAttributeMaxDynamicSharedMemorySize, K8_SMEM);
    k8_gemm<<<(N + 127) / 128, 512, K8_SMEM, g_s1>>>(b, N);
    cudaEventRecord(g_ev1, g_s1);

    k2_c0<<<1, 512>>>(N);
    k3_d2<<<1184, 256>>>(N);
    k45_Zc<<<592, 256>>>(z, N);
    k7_norm<<<1, 512>>>(b);
    k6_v<<<32, 512>>>(W);
    k9_dot<<<1184, 256>>>(N);

    cudaStreamWaitEvent(0, g_ev1, 0);
    k10_final<<<(N + 255) / 256, 256>>>(out, N);
}

// round 9
// speedup vs baseline: 1.0310x; 1.0310x over previous
#include <cuda_runtime.h>
#include <cuda_bf16.h>
#include <cstdint>

#define DD 512
#define MAXN 200000
#define TAU_INV 2.0f
#define EPS 1e-8f

// ---------------- device scratch (no allocations allowed) ----------------
__device__ __align__(256) __nv_bfloat16 g_zbf[(size_t)MAXN * DD];  // z bf16
__device__ __align__(256) __nv_bfloat16 g_wbf[DD * DD];            // W bf16
__device__ float g_s[MAXN];                          // row sumsq of z
__device__ float g_d2[MAXN];
__device__ float g_dot[MAXN];                        // z . v
__device__ float g_nsq[MAXN];                        // ||x_proj||^2
__device__ float g_colsum[DD];
__device__ float g_c0[DD];
__device__ float g_cp[DD];                           // unnormalized centroid
__device__ float g_c[DD];                            // centroid
__device__ float g_v[DD];                            // v = W^T c (fp32)
__device__ float g_cc;                               // ||c0||^2
__device__ float g_Z;
__device__ float g_bc;                               // b . c
__device__ float g_cnorm;
__device__ int   g_d2min_bits;

// ---------------- streams/events for parallel graph branches -------------
static cudaStream_t g_s1;
static cudaEvent_t g_ev0, g_evZ, g_ev1;
static struct StreamInit {
    StreamInit() {
        cudaStreamCreateWithFlags(&g_s1, cudaStreamNonBlocking);
        cudaEventCreateWithFlags(&g_ev0, cudaEventDisableTiming);
        cudaEventCreateWithFlags(&g_evZ, cudaEventDisableTiming);
        cudaEventCreateWithFlags(&g_ev1, cudaEventDisableTiming);
    }
} g_stream_init;

// ---------------- helpers ----------------
__device__ __forceinline__ uint32_t smem_u32(const void* p) {
    return (uint32_t)__cvta_generic_to_shared(p);
}
__device__ __forceinline__ void ldmx4(uint32_t* r, uint32_t addr) {
    asm volatile("ldmatrix.sync.aligned.m8n8.x4.shared.b16 {%0,%1,%2,%3}, [%4];"
                 : "=r"(r[0]), "=r"(r[1]), "=r"(r[2]), "=r"(r[3]) : "r"(addr));
}
__device__ __forceinline__ void mma16816(float* c, const uint32_t* a, const uint32_t* b) {
    asm volatile("mma.sync.aligned.m16n8k16.row.col.f32.bf16.bf16.f32 "
                 "{%0,%1,%2,%3}, {%4,%5,%6,%7}, {%8,%9}, {%0,%1,%2,%3};"
                 : "+f"(c[0]), "+f"(c[1]), "+f"(c[2]), "+f"(c[3])
                 : "r"(a[0]), "r"(a[1]), "r"(a[2]), "r"(a[3]), "r"(b[0]), "r"(b[1]));
}
__device__ __forceinline__ void cp_async16(uint32_t sdst, const void* gsrc) {
    asm volatile("cp.async.cg.shared.global [%0], [%1], 16;"
                 :: "r"(sdst), "l"(gsrc) : "memory");
}
__device__ __forceinline__ void cp_commit() {
    asm volatile("cp.async.commit_group;" ::: "memory");
}
__device__ __forceinline__ void cp_wait1() {
    asm volatile("cp.async.wait_group 1;" ::: "memory");
}

// ================= k0a: zero accumulators =================
__global__ void k0a_zero() {
    int i = blockIdx.x * blockDim.x + threadIdx.x;
    if (i < DD) { g_colsum[i] = 0.f; g_cp[i] = 0.f; g_v[i] = 0.f; }
    if (i == DD) g_Z = 0.f;
    if (i == DD + 1) g_d2min_bits = 0x7f7fffff;
}

// ================= k0b: W -> bf16 (side stream) =================
__global__ void k0b_wcvt(const float* __restrict__ W) {
    int i = blockIdx.x * blockDim.x + threadIdx.x;
    int stride = gridDim.x * blockDim.x;
    for (int j = i; j < DD * DD; j += stride) g_wbf[j] = __float2bfloat16(W[j]);
}

// ================= k1: colsums + row sumsq + z->bf16 =================
__global__ void k1_pass1(const float* __restrict__ z, int N) {
    __shared__ float scol[DD];
    const int tid = threadIdx.x, wid = tid >> 5, lane = tid & 31;
    for (int i = tid; i < DD; i += blockDim.x) scol[i] = 0.f;
    __syncthreads();
    const int gw = blockIdx.x * (blockDim.x >> 5) + wid;
    const int nw = gridDim.x * (blockDim.x >> 5);
    float cs[16];
#pragma unroll
    for (int i = 0; i < 16; i++) cs[i] = 0.f;
    for (int row = gw; row < N; row += nw) {
        const float4* zr = (const float4*)(z + (size_t)row * DD);
        float ssq = 0.f;
#pragma unroll
        for (int c = 0; c < 4; c++) {
            float4 v = __ldcs(zr + c * 32 + lane);
            ssq += v.x * v.x + v.y * v.y + v.z * v.z + v.w * v.w;
            cs[c * 4 + 0] += v.x; cs[c * 4 + 1] += v.y;
            cs[c * 4 + 2] += v.z; cs[c * 4 + 3] += v.w;
            __nv_bfloat162 b0 = __floats2bfloat162_rn(v.x, v.y);
            __nv_bfloat162 b1 = __floats2bfloat162_rn(v.z, v.w);
            float2 u;
            u.x = __uint_as_float(*reinterpret_cast<uint32_t*>(&b0));
            u.y = __uint_as_float(*reinterpret_cast<uint32_t*>(&b1));
            __stcs((float2*)(g_zbf + (size_t)row * DD + c * 128 + lane * 4), u);
        }
#pragma unroll
        for (int o = 16; o > 0; o >>= 1) ssq += __shfl_xor_sync(0xffffffffu, ssq, o);
        if (lane == 0) g_s[row] = ssq;
    }
#pragma unroll
    for (int c = 0; c < 4; c++)
#pragma unroll
        for (int e = 0; e < 4; e++)
            atomicAdd(&scol[c * 128 + lane * 4 + e], cs[c * 4 + e]);
    __syncthreads();
    for (int i = tid; i < DD; i += blockDim.x) atomicAdd(&g_colsum[i], scol[i]);
}

// ================= k2: c0 = colsum/N, cc = ||c0||^2 =================
__global__ void k2_c0(int N) {
    __shared__ float red[16];
    const int tid = threadIdx.x; // 512
    float c0 = g_colsum[tid] / (float)N;
    g_c0[tid] = c0;
    float sq = c0 * c0;
#pragma unroll
    for (int o = 16; o > 0; o >>= 1) sq += __shfl_xor_sync(0xffffffffu, sq, o);
    if ((tid & 31) == 0) red[tid >> 5] = sq;
    __syncthreads();
    if (tid < 16) {
        float s = red[tid];
#pragma unroll
        for (int o = 8; o > 0; o >>= 1) s += __shfl_xor_sync(0xffffu, s, o);
        if (tid == 0) g_cc = s;
    }
}

// ================= k3: d2 = s - 2 h.c0 + cc (bf16 h), block-min ==========
__global__ void k3_d2(int N) {
    __shared__ __align__(16) float c0s[DD];
    __shared__ int smin;
    const int tid = threadIdx.x, wid = tid >> 5, lane = tid & 31;
    for (int i = tid; i < DD; i += blockDim.x) c0s[i] = g_c0[i];
    if (tid == 0) smin = 0x7f7fffff;
    __syncthreads();
    const float cc = g_cc;
    const int gw = blockIdx.x * (blockDim.x >> 5) + wid;
    const int nw = gridDim.x * (blockDim.x >> 5);
    for (int r4 = gw * 4; r4 < N; r4 += nw * 4) {
        float t[4] = {0.f, 0.f, 0.f, 0.f};
        int nr = (N - r4 < 4) ? (N - r4) : 4;
#pragma unroll
        for (int q = 0; q < 4; q++) {
            int row = r4 + ((q < nr) ? q : 0);
#pragma unroll
            for (int c = 0; c < 2; c++) {
                uint4 u = __ldcs((const uint4*)(g_zbf + (size_t)row * DD + c * 256 + lane * 8));
                const __nv_bfloat162* p = (const __nv_bfloat162*)&u;
                float4 cv0 = ((const float4*)c0s)[c * 64 + lane * 2];
                float4 cv1 = ((const float4*)c0s)[c * 64 + lane * 2 + 1];
                float2 f0 = __bfloat1622float2(p[0]);
                float2 f1 = __bfloat1622float2(p[1]);
                float2 f2 = __bfloat1622float2(p[2]);
                float2 f3 = __bfloat1622float2(p[3]);
                t[q] += f0.x * cv0.x + f0.y * cv0.y + f1.x * cv0.z + f1.y * cv0.w
                      + f2.x * cv1.x + f2.y * cv1.y + f3.x * cv1.z + f3.y * cv1.w;
            }
        }
#pragma unroll
        for (int q = 0; q < 4; q++)
#pragma unroll
            for (int o = 16; o > 0; o >>= 1)
                t[q] += __shfl_xor_sync(0xffffffffu, t[q], o);
        if (lane == 0) {
            int lmin = 0x7f7fffff;
#pragma unroll
            for (int q = 0; q < 4; q++) {
                if (q < nr) {
                    float d2 = g_s[r4 + q] - 2.f * t[q] + cc;
                    g_d2[r4 + q] = d2;
                    int bits = __float_as_int(d2);
                    if (bits < lmin) lmin = bits;
                }
            }
            atomicMin(&smin, lmin);
        }
    }
    __syncthreads();
    if (tid == 0) atomicMin(&g_d2min_bits, smin);
}

// ================= k45: Z + unnormalized centroid c' =====================
__global__ void k45_Zc(const float* __restrict__ z, int N) {
    __shared__ float red[8];
    const int tid = threadIdx.x, lane = tid & 31;
    const float d2min = __int_as_float(g_d2min_bits);
    const int gidx = blockIdx.x * blockDim.x + tid;
    const int stride = gridDim.x * blockDim.x;
    const int numIter = (N + stride - 1) / stride;
    float zpart = 0.f;
    for (int i = 0; i < numIter; i++) {
        int r = gidx + i * stride;
        float e = 0.f;
        if (r < N) e = __expf((d2min - g_d2[r]) * TAU_INV);
        zpart += e;
        unsigned mask = __ballot_sync(0xffffffffu, e > 1e-13f);
        while (mask) {
            int src = __ffs(mask) - 1;
            mask &= mask - 1;
            int rb = __shfl_sync(0xffffffffu, r, src);
            float eb = __shfl_sync(0xffffffffu, e, src);
            const float* zr = z + (size_t)rb * DD;
#pragma unroll
            for (int c = 0; c < 16; c++)
                atomicAdd(&g_cp[c * 32 + lane], eb * zr[c * 32 + lane]);
        }
    }
#pragma unroll
    for (int o = 16; o > 0; o >>= 1) zpart += __shfl_xor_sync(0xffffffffu, zpart, o);
    if (lane == 0) red[tid >> 5] = zpart;
    __syncthreads();
    if (tid < 8) {
        float t = red[tid];
#pragma unroll
        for (int o = 4; o > 0; o >>= 1) t += __shfl_xor_sync(0xffu, t, o);
        if (tid == 0) atomicAdd(&g_Z, t);
    }
}

// ================= k7: c = c'/Z, cnorm, bc =================
__global__ void k7_norm(const float* __restrict__ b) {
    __shared__ float redc[16], redb[16];
    const int tid = threadIdx.x; // 512
    const float invZ = 1.f / g_Z;
    float cv = g_cp[tid] * invZ;
    g_c[tid] = cv;
    float pc = cv * cv;
    float pb = cv * b[tid];
#pragma unroll
    for (int o = 16; o > 0; o >>= 1) {
        pc += __shfl_xor_sync(0xffffffffu, pc, o);
        pb += __shfl_xor_sync(0xffffffffu, pb, o);
    }
    if ((tid & 31) == 0) { redc[tid >> 5] = pc; redb[tid >> 5] = pb; }
    __syncthreads();
    if (tid < 16) {
        float sc = redc[tid], sb = redb[tid];
#pragma unroll
        for (int o = 8; o > 0; o >>= 1) {
            sc += __shfl_xor_sync(0xffffu, sc, o);
            sb += __shfl_xor_sync(0xffffu, sb, o);
        }
        if (tid == 0) { g_cnorm = fmaxf(sqrtf(sc), EPS); g_bc = sb; }
    }
}

// ================= k6: v = W^T c (fp32 exact) =================
__global__ void k6_v(const float* __restrict__ W) {
    __shared__ float cs[16];
    const int tid = threadIdx.x; // 512
    const int j0 = blockIdx.x * 16;
    if (tid < 16) cs[tid] = g_c[j0 + tid];
    __syncthreads();
    float acc = 0.f;
#pragma unroll
    for (int jj = 0; jj < 16; jj++)
        acc += cs[jj] * W[(size_t)(j0 + jj) * DD + tid];
    atomicAdd(&g_v[tid], acc);
}

// ================= k9: dot_i = z_i . v (bf16 z) =================
__global__ void k9_dot(int N) {
    __shared__ __align__(16) float sv[DD];
    const int tid = threadIdx.x, wid = tid >> 5, lane = tid & 31;
    for (int i = tid; i < DD; i += blockDim.x) sv[i] = g_v[i];
    __syncthreads();
    const int gw = blockIdx.x * (blockDim.x >> 5) + wid;
    const int nw = gridDim.x * (blockDim.x >> 5);
    for (int row = gw; row < N; row += nw) {
        float d = 0.f;
#pragma unroll
        for (int c = 0; c < 2; c++) {
            uint4 u = __ldcs((const uint4*)(g_zbf + (size_t)row * DD + c * 256 + lane * 8));
            const __nv_bfloat162* p = (const __nv_bfloat162*)&u;
            float4 v0 = ((const float4*)sv)[c * 64 + lane * 2];
            float4 v1 = ((const float4*)sv)[c * 64 + lane * 2 + 1];
            float2 f0 = __bfloat1622float2(p[0]);
            float2 f1 = __bfloat1622float2(p[1]);
            float2 f2 = __bfloat1622float2(p[2]);
            float2 f3 = __bfloat1622float2(p[3]);
            d += f0.x * v0.x + f0.y * v0.y + f1.x * v0.z + f1.y * v0.w
               + f2.x * v1.x + f2.y * v1.y + f3.x * v1.z + f3.y * v1.w;
        }
#pragma unroll
        for (int o = 16; o > 0; o >>= 1) d += __shfl_xor_sync(0xffffffffu, d, o);
        if (lane == 0) g_dot[row] = d;
    }
}

// ================= k8: bf16 mma GEMM, warp tile m64 x j64 =================
// 256 threads / 8 warps: 2 m-groups (m64) x 4 j-groups (j64) = m128 x j256.
// B stream: j256 x k64 (32 KB) double-buffered; 2 jc chunks x 8 kq = 16 its.
// A resident 128 KB. MMA:LDSM ratio 4.0 (32 mma per 8 ldmx4 per k16 step).
#define K8_A    0
#define K8_B    131072
#define K8_BB   32768
#define K8_BV   196608
#define K8_NSQ  198656
#define K8_SMEM 199680

__global__ void __launch_bounds__(256, 1)
k8_gemm(const float* __restrict__ b_in, int N) {
    extern __shared__ char smem[];
    const uint32_t sbase = smem_u32(smem);
    const int tid = threadIdx.x, warp = tid >> 5, lane = tid & 31;
    const int m0 = blockIdx.x * 128;

    float* sbv = (float*)(smem + K8_BV);
    float* snq = (float*)(smem + K8_NSQ);
    for (int i = tid; i < DD; i += 256) sbv[i] = b_in[i];
    if (tid < 128) snq[tid] = 0.f;

    // ---- prefetch B buffers 0 and 1 (j256 x k64, pitch 128B) ----
#pragma unroll 1
    for (int h = 0; h < 2; h++) {
        const uint32_t bbuf = sbase + K8_B + (h & 1) * K8_BB;
        const int jc = h >> 3, kq = h & 7;
#pragma unroll
        for (int it = 0; it < 8; it++) {
            int idx = it * 256 + tid;
            int j = idx >> 3, ci = idx & 7;
            cp_async16(bbuf + j * 128 + ((ci ^ (j & 7)) << 4),
                       g_wbf + (size_t)(jc * 256 + j) * DD + kq * 64 + ci * 8);
        }
        cp_commit();
    }

    // ---- load A: 128 rows x 512 bf16, pitch 1024, XOR swizzle ----
#pragma unroll
    for (int it = 0; it < 32; it++) {
        int idx = it * 256 + tid;
        int r = idx >> 6, ci = idx & 63;
        int grow = m0 + r; if (grow > N - 1) grow = N - 1;
        uint4 val = *(const uint4*)(g_zbf + (size_t)grow * DD + ci * 8);
        *(uint4*)(smem + K8_A + r * 1024 + ((ci ^ (r & 7)) << 4)) = val;
    }

    // ---- warp coords: mg = warp&1 (m64), jg = warp>>1 (j64 of j256) ----
    const int mg = warp & 1, jg = warp >> 1;
    const int mbase = mg * 64;
    const uint32_t swa = lane & 7;
    const uint32_t a0base = sbase + K8_A + (uint32_t)(mbase + (lane & 15)) * 1024;
    const int jrow = (lane & 7) + ((lane >> 4) << 3);
    const uint32_t brow_off = (uint32_t)(jg * 64 + jrow) * 128;
    const uint32_t ciBofs = (lane >> 3) & 1;
    const uint32_t ciAofs = lane >> 4;

    float acc[32][4];
#pragma unroll
    for (int t = 0; t < 32; t++)
#pragma unroll
        for (int e = 0; e < 4; e++) acc[t][e] = 0.f;
    float nsq[4][2] = {{0.f,0.f},{0.f,0.f},{0.f,0.f},{0.f,0.f}};

    for (int h = 0; h < 16; h++) {           // jc = h>>3 (j256), kq = h&7 (k64)
        const int buf = h & 1, jc = h >> 3, kq = h & 7;
        cp_wait1();
        __syncthreads();
        const uint32_t b0base = sbase + K8_B + buf * K8_BB + brow_off;

#pragma unroll
        for (int ktl = 0; ktl < 4; ktl++) {  // k16 steps within k64
            uint32_t a[4][4], bb[4][4];
            uint32_t ciA = (uint32_t)(kq * 4 + ktl) * 2 + ciAofs;
            uint32_t adr = a0base + ((ciA ^ swa) << 4);
            ldmx4(a[0], adr);
            ldmx4(a[1], adr + 16 * 1024);
            ldmx4(a[2], adr + 32 * 1024);
            ldmx4(a[3], adr + 48 * 1024);
            uint32_t ciB = (uint32_t)ktl * 2 + ciBofs;
            uint32_t bdr = b0base + ((ciB ^ swa) << 4);
            ldmx4(bb[0], bdr);
            ldmx4(bb[1], bdr + 16 * 128);
            ldmx4(bb[2], bdr + 32 * 128);
            ldmx4(bb[3], bdr + 48 * 128);
#pragma unroll
            for (int mt = 0; mt < 4; mt++) {
                // a[mt] covers rows mbase+mt*16..+15 (m16); 8 j-tiles of n8
                float* arow = (float*)acc[mt * 8];
#pragma unroll
                for (int nt = 0; nt < 8; nt++)
                    mma16816(acc[mt * 8 + nt], a[mt], bb[nt >> 1] + (nt & 1) * 2);
            }
        }
        __syncthreads();   // all warps done with buf before refill

        if (kq == 7) {
            // j256 chunk complete over k512: fold (acc + b)^2, reset acc
#pragma unroll
            for (int mt = 0; mt < 4; mt++)
#pragma unroll
                for (int nt = 0; nt < 8; nt++) {
                    int jglob = jc * 256 + jg * 64 + nt * 8 + (lane & 3) * 2;
                    float bx = sbv[jglob], by = sbv[jglob + 1];
                    float* a = acc[mt * 8 + nt];
                    float v0 = a[0] + bx, v1 = a[1] + by;
                    float v2 = a[2] + bx, v3 = a[3] + by;
                    nsq[mt][0] += v0 * v0 + v1 * v1;
                    nsq[mt][1] += v2 * v2 + v3 * v3;
                    a[0] = 0.f; a[1] = 0.f; a[2] = 0.f; a[3] = 0.f;
                }
        }
        if (h + 2 < 16) {
            const int h2 = h + 2;
            const uint32_t bbuf = sbase + K8_B + buf * K8_BB;
            const int jc2 = h2 >> 3, kq2 = h2 & 7;
#pragma unroll
            for (int it = 0; it < 8; it++) {
                int idx = it * 256 + tid;
                int j = idx >> 3, ci = idx & 7;
                cp_async16(bbuf + j * 128 + ((ci ^ (j & 7)) << 4),
                           g_wbf + (size_t)(jc2 * 256 + j) * DD + kq2 * 64 + ci * 8);
            }
        }
        cp_commit();
    }

    // ---- merge lane partials: quad lanes share a row; 4 j-groups merge ----
#pragma unroll
    for (int mt = 0; mt < 4; mt++)
#pragma unroll
        for (int hh = 0; hh < 2; hh++) {
            float vn = nsq[mt][hh];
            vn += __shfl_xor_sync(0xffffffffu, vn, 1);
            vn += __shfl_xor_sync(0xffffffffu, vn, 2);
            if ((lane & 3) == 0)
                atomicAdd(&snq[mbase + mt * 16 + hh * 8 + (lane >> 2)], vn);
        }
    __syncthreads();

    if (tid < 128 && m0 + tid < N) g_nsq[m0 + tid] = snq[tid];
}

// ================= k10: finalize dist =================
__global__ void k10_final(float* __restrict__ out, int N) {
    int i = blockIdx.x * blockDim.x + threadIdx.x;
    if (i < N) {
        float nx = fmaxf(sqrtf(g_nsq[i]), EPS);
        out[i] = 1.0f - (g_dot[i] + g_bc) / (nx * g_cnorm);
    }
}

// ================= launch (forked graph) =================
extern "C" void kernel_launch(void* const* d_in, const int* in_sizes, int n_in,
                              void* d_out, int out_size) {
    const float* z = (const float*)d_in[0];
    const float* W = (const float*)d_in[1];
    const float* b = (const float*)d_in[2];
    float* out = (float*)d_out;
    const int N = in_sizes[0] / DD;

    cudaEventRecord(g_ev0, 0);
    cudaStreamWaitEvent(g_s1, g_ev0, 0);

    k0b_wcvt<<<512, 256, 0, g_s1>>>(W);

    k0a_zero<<<3, 256>>>();
    k1_pass1<<<1184, 256>>>(z, N);

    cudaEventRecord(g_evZ, 0);
    cudaStreamWaitEvent(g_s1, g_evZ, 0);
    cudaFuncSetAttribute(k8_gemm, cudaFuncAttributeMaxDynamicSharedMemorySize, K8_SMEM);
    k8_gemm<<<(N + 127) / 128, 256, K8_SMEM, g_s1>>>(b, N);
    cudaEventRecord(g_ev1, g_s1);

    k2_c0<<<1, 512>>>(N);
    k3_d2<<<1184, 256>>>(N);
    k45_Zc<<<592, 256>>>(z, N);
    k7_norm<<<1, 512>>>(b);
    k6_v<<<32, 512>>>(W);
    k9_dot<<<1184, 256>>>(N);

    cudaStreamWaitEvent(0, g_ev1, 0);
    k10_final<<<(N + 255) / 256, 256>>>(out, N);
}

// round 10
// speedup vs baseline: 1.0440x; 1.0125x over previous
#include <cuda_runtime.h>
#include <cuda_bf16.h>
#include <cstdint>

#define DD 512
#define MAXN 200000
#define TAU_INV 2.0f
#define EPS 1e-8f

// ---------------- device scratch (no allocations allowed) ----------------
__device__ __align__(256) __nv_bfloat16 g_zbf[(size_t)MAXN * DD];  // z bf16
__device__ __align__(256) __nv_bfloat16 g_wbf[DD * DD];            // W bf16
__device__ float g_s[MAXN];                          // row sumsq of z
__device__ float g_d2[MAXN];
__device__ float g_dot[MAXN];                        // z . v
__device__ float g_nsq[MAXN];                        // ||x_proj||^2
__device__ float g_colsum[DD];
__device__ float g_c0[DD];
__device__ float g_cp[DD];                           // unnormalized centroid
__device__ float g_c[DD];                            // centroid
__device__ float g_v[DD];                            // v = W^T c (fp32)
__device__ float g_cc;                               // ||c0||^2
__device__ float g_Z;
__device__ float g_bc;                               // b . c
__device__ float g_cnorm;
__device__ int   g_d2min_bits;

// ---------------- streams/events for parallel graph branches -------------
static cudaStream_t g_s1;
static cudaEvent_t g_ev0, g_ev1;
static struct StreamInit {
    StreamInit() {
        cudaStreamCreateWithFlags(&g_s1, cudaStreamNonBlocking);
        cudaEventCreateWithFlags(&g_ev0, cudaEventDisableTiming);
        cudaEventCreateWithFlags(&g_ev1, cudaEventDisableTiming);
    }
} g_stream_init;

// ---------------- helpers ----------------
__device__ __forceinline__ uint32_t smem_u32(const void* p) {
    return (uint32_t)__cvta_generic_to_shared(p);
}
__device__ __forceinline__ void ldmx4(uint32_t* r, uint32_t addr) {
    asm volatile("ldmatrix.sync.aligned.m8n8.x4.shared.b16 {%0,%1,%2,%3}, [%4];"
                 : "=r"(r[0]), "=r"(r[1]), "=r"(r[2]), "=r"(r[3]) : "r"(addr));
}
__device__ __forceinline__ void mma16816(float* c, const uint32_t* a, const uint32_t* b) {
    asm volatile("mma.sync.aligned.m16n8k16.row.col.f32.bf16.bf16.f32 "
                 "{%0,%1,%2,%3}, {%4,%5,%6,%7}, {%8,%9}, {%0,%1,%2,%3};"
                 : "+f"(c[0]), "+f"(c[1]), "+f"(c[2]), "+f"(c[3])
                 : "r"(a[0]), "r"(a[1]), "r"(a[2]), "r"(a[3]), "r"(b[0]), "r"(b[1]));
}
__device__ __forceinline__ void cp_async16(uint32_t sdst, const void* gsrc) {
    asm volatile("cp.async.cg.shared.global [%0], [%1], 16;"
                 :: "r"(sdst), "l"(gsrc) : "memory");
}
__device__ __forceinline__ void cp_commit() {
    asm volatile("cp.async.commit_group;" ::: "memory");
}
__device__ __forceinline__ void cp_wait1() {
    asm volatile("cp.async.wait_group 1;" ::: "memory");
}

// ================= k0a: zero accumulators =================
__global__ void k0a_zero() {
    int i = blockIdx.x * blockDim.x + threadIdx.x;
    if (i < DD) { g_colsum[i] = 0.f; g_cp[i] = 0.f; g_v[i] = 0.f; }
    if (i == DD) g_Z = 0.f;
    if (i == DD + 1) g_d2min_bits = 0x7f7fffff;
}

// ================= k0b: W -> bf16 (side stream) =================
__global__ void k0b_wcvt(const float* __restrict__ W) {
    int i = blockIdx.x * blockDim.x + threadIdx.x;
    int stride = gridDim.x * blockDim.x;
    for (int j = i; j < DD * DD; j += stride) g_wbf[j] = __float2bfloat16(W[j]);
}

// ================= k1: colsums + row sumsq + z->bf16 =================
__global__ void k1_pass1(const float* __restrict__ z, int N) {
    __shared__ float scol[DD];
    const int tid = threadIdx.x, wid = tid >> 5, lane = tid & 31;
    for (int i = tid; i < DD; i += blockDim.x) scol[i] = 0.f;
    __syncthreads();
    const int gw = blockIdx.x * (blockDim.x >> 5) + wid;
    const int nw = gridDim.x * (blockDim.x >> 5);
    float cs[16];
#pragma unroll
    for (int i = 0; i < 16; i++) cs[i] = 0.f;
    for (int row = gw; row < N; row += nw) {
        const float4* zr = (const float4*)(z + (size_t)row * DD);
        float ssq = 0.f;
#pragma unroll
        for (int c = 0; c < 4; c++) {
            float4 v = zr[c * 32 + lane];
            ssq += v.x * v.x + v.y * v.y + v.z * v.z + v.w * v.w;
            cs[c * 4 + 0] += v.x; cs[c * 4 + 1] += v.y;
            cs[c * 4 + 2] += v.z; cs[c * 4 + 3] += v.w;
            __nv_bfloat162 b0 = __floats2bfloat162_rn(v.x, v.y);
            __nv_bfloat162 b1 = __floats2bfloat162_rn(v.z, v.w);
            float2 u;
            u.x = __uint_as_float(*reinterpret_cast<uint32_t*>(&b0));
            u.y = __uint_as_float(*reinterpret_cast<uint32_t*>(&b1));
            __stcs((float2*)(g_zbf + (size_t)row * DD + c * 128 + lane * 4), u);
        }
#pragma unroll
        for (int o = 16; o > 0; o >>= 1) ssq += __shfl_xor_sync(0xffffffffu, ssq, o);
        if (lane == 0) g_s[row] = ssq;
    }
#pragma unroll
    for (int c = 0; c < 4; c++)
#pragma unroll
        for (int e = 0; e < 4; e++)
            atomicAdd(&scol[c * 128 + lane * 4 + e], cs[c * 4 + e]);
    __syncthreads();
    for (int i = tid; i < DD; i += blockDim.x) atomicAdd(&g_colsum[i], scol[i]);
}

// ================= k2: c0 = colsum/N, cc = ||c0||^2 =================
__global__ void k2_c0(int N) {
    __shared__ float red[16];
    const int tid = threadIdx.x; // 512
    float c0 = g_colsum[tid] / (float)N;
    g_c0[tid] = c0;
    float sq = c0 * c0;
#pragma unroll
    for (int o = 16; o > 0; o >>= 1) sq += __shfl_xor_sync(0xffffffffu, sq, o);
    if ((tid & 31) == 0) red[tid >> 5] = sq;
    __syncthreads();
    if (tid < 16) {
        float s = red[tid];
#pragma unroll
        for (int o = 8; o > 0; o >>= 1) s += __shfl_xor_sync(0xffffu, s, o);
        if (tid == 0) g_cc = s;
    }
}

// ================= k3: d2 = s - 2 h.c0 + cc (bf16 h), block-min ==========
__global__ void k3_d2(int N) {
    __shared__ __align__(16) float c0s[DD];
    __shared__ int smin;
    const int tid = threadIdx.x, wid = tid >> 5, lane = tid & 31;
    for (int i = tid; i < DD; i += blockDim.x) c0s[i] = g_c0[i];
    if (tid == 0) smin = 0x7f7fffff;
    __syncthreads();
    const float cc = g_cc;
    const int gw = blockIdx.x * (blockDim.x >> 5) + wid;
    const int nw = gridDim.x * (blockDim.x >> 5);
    for (int r4 = gw * 4; r4 < N; r4 += nw * 4) {
        float t[4] = {0.f, 0.f, 0.f, 0.f};
        int nr = (N - r4 < 4) ? (N - r4) : 4;
#pragma unroll
        for (int q = 0; q < 4; q++) {
            int row = r4 + ((q < nr) ? q : 0);
#pragma unroll
            for (int c = 0; c < 2; c++) {
                uint4 u = __ldcs((const uint4*)(g_zbf + (size_t)row * DD + c * 256 + lane * 8));
                const __nv_bfloat162* p = (const __nv_bfloat162*)&u;
                float4 cv0 = ((const float4*)c0s)[c * 64 + lane * 2];
                float4 cv1 = ((const float4*)c0s)[c * 64 + lane * 2 + 1];
                float2 f0 = __bfloat1622float2(p[0]);
                float2 f1 = __bfloat1622float2(p[1]);
                float2 f2 = __bfloat1622float2(p[2]);
                float2 f3 = __bfloat1622float2(p[3]);
                t[q] += f0.x * cv0.x + f0.y * cv0.y + f1.x * cv0.z + f1.y * cv0.w
                      + f2.x * cv1.x + f2.y * cv1.y + f3.x * cv1.z + f3.y * cv1.w;
            }
        }
#pragma unroll
        for (int q = 0; q < 4; q++)
#pragma unroll
            for (int o = 16; o > 0; o >>= 1)
                t[q] += __shfl_xor_sync(0xffffffffu, t[q], o);
        if (lane == 0) {
            int lmin = 0x7f7fffff;
#pragma unroll
            for (int q = 0; q < 4; q++) {
                if (q < nr) {
                    float d2 = g_s[r4 + q] - 2.f * t[q] + cc;
                    g_d2[r4 + q] = d2;
                    int bits = __float_as_int(d2);
                    if (bits < lmin) lmin = bits;
                }
            }
            atomicMin(&smin, lmin);
        }
    }
    __syncthreads();
    if (tid == 0) atomicMin(&g_d2min_bits, smin);
}

// ================= k45: Z + unnormalized centroid c' =====================
__global__ void k45_Zc(const float* __restrict__ z, int N) {
    __shared__ float red[8];
    const int tid = threadIdx.x, lane = tid & 31;
    const float d2min = __int_as_float(g_d2min_bits);
    const int gidx = blockIdx.x * blockDim.x + tid;
    const int stride = gridDim.x * blockDim.x;
    const int numIter = (N + stride - 1) / stride;
    float zpart = 0.f;
    for (int i = 0; i < numIter; i++) {
        int r = gidx + i * stride;
        float e = 0.f;
        if (r < N) e = __expf((d2min - g_d2[r]) * TAU_INV);
        zpart += e;
        unsigned mask = __ballot_sync(0xffffffffu, e > 1e-13f);
        while (mask) {
            int src = __ffs(mask) - 1;
            mask &= mask - 1;
            int rb = __shfl_sync(0xffffffffu, r, src);
            float eb = __shfl_sync(0xffffffffu, e, src);
            const float* zr = z + (size_t)rb * DD;
#pragma unroll
            for (int c = 0; c < 16; c++)
                atomicAdd(&g_cp[c * 32 + lane], eb * zr[c * 32 + lane]);
        }
    }
#pragma unroll
    for (int o = 16; o > 0; o >>= 1) zpart += __shfl_xor_sync(0xffffffffu, zpart, o);
    if (lane == 0) red[tid >> 5] = zpart;
    __syncthreads();
    if (tid < 8) {
        float t = red[tid];
#pragma unroll
        for (int o = 4; o > 0; o >>= 1) t += __shfl_xor_sync(0xffu, t, o);
        if (tid == 0) atomicAdd(&g_Z, t);
    }
}

// ================= k7: c = c'/Z, cnorm, bc =================
__global__ void k7_norm(const float* __restrict__ b) {
    __shared__ float redc[16], redb[16];
    const int tid = threadIdx.x; // 512
    const float invZ = 1.f / g_Z;
    float cv = g_cp[tid] * invZ;
    g_c[tid] = cv;
    float pc = cv * cv;
    float pb = cv * b[tid];
#pragma unroll
    for (int o = 16; o > 0; o >>= 1) {
        pc += __shfl_xor_sync(0xffffffffu, pc, o);
        pb += __shfl_xor_sync(0xffffffffu, pb, o);
    }
    if ((tid & 31) == 0) { redc[tid >> 5] = pc; redb[tid >> 5] = pb; }
    __syncthreads();
    if (tid < 16) {
        float sc = redc[tid], sb = redb[tid];
#pragma unroll
        for (int o = 8; o > 0; o >>= 1) {
            sc += __shfl_xor_sync(0xffffu, sc, o);
            sb += __shfl_xor_sync(0xffffu, sb, o);
        }
        if (tid == 0) { g_cnorm = fmaxf(sqrtf(sc), EPS); g_bc = sb; }
    }
}

// ================= k6: v = W^T c (fp32 exact) =================
__global__ void k6_v(const float* __restrict__ W) {
    __shared__ float cs[16];
    const int tid = threadIdx.x; // 512
    const int j0 = blockIdx.x * 16;
    if (tid < 16) cs[tid] = g_c[j0 + tid];
    __syncthreads();
    float acc = 0.f;
#pragma unroll
    for (int jj = 0; jj < 16; jj++)
        acc += cs[jj] * W[(size_t)(j0 + jj) * DD + tid];
    atomicAdd(&g_v[tid], acc);
}

// ================= k9: dot_i = z_i . v (bf16 z) =================
__global__ void k9_dot(int N) {
    __shared__ __align__(16) float sv[DD];
    const int tid = threadIdx.x, wid = tid >> 5, lane = tid & 31;
    for (int i = tid; i < DD; i += blockDim.x) sv[i] = g_v[i];
    __syncthreads();
    const int gw = blockIdx.x * (blockDim.x >> 5) + wid;
    const int nw = gridDim.x * (blockDim.x >> 5);
    for (int row = gw; row < N; row += nw) {
        float d = 0.f;
#pragma unroll
        for (int c = 0; c < 2; c++) {
            uint4 u = __ldcs((const uint4*)(g_zbf + (size_t)row * DD + c * 256 + lane * 8));
            const __nv_bfloat162* p = (const __nv_bfloat162*)&u;
            float4 v0 = ((const float4*)sv)[c * 64 + lane * 2];
            float4 v1 = ((const float4*)sv)[c * 64 + lane * 2 + 1];
            float2 f0 = __bfloat1622float2(p[0]);
            float2 f1 = __bfloat1622float2(p[1]);
            float2 f2 = __bfloat1622float2(p[2]);
            float2 f3 = __bfloat1622float2(p[3]);
            d += f0.x * v0.x + f0.y * v0.y + f1.x * v0.z + f1.y * v0.w
               + f2.x * v1.x + f2.y * v1.y + f3.x * v1.z + f3.y * v1.w;
        }
#pragma unroll
        for (int o = 16; o > 0; o >>= 1) d += __shfl_xor_sync(0xffffffffu, d, o);
        if (lane == 0) g_dot[row] = d;
    }
}

// ================= k8: bf16 mma GEMM, reads z fp32 directly ===============
// A tile converted fp32->bf16 in-register at load: NO dependency on k1, so
// the GEMM overlaps the entire centroid chain. Warp tile m64 x j64 (R9).
#define K8_A    0
#define K8_B    131072
#define K8_BB   32768
#define K8_BV   196608
#define K8_NSQ  198656
#define K8_SMEM 199680

__global__ void __launch_bounds__(256, 1)
k8_gemm(const float* __restrict__ z, const float* __restrict__ b_in, int N) {
    extern __shared__ char smem[];
    const uint32_t sbase = smem_u32(smem);
    const int tid = threadIdx.x, warp = tid >> 5, lane = tid & 31;
    const int m0 = blockIdx.x * 128;

    float* sbv = (float*)(smem + K8_BV);
    float* snq = (float*)(smem + K8_NSQ);
    for (int i = tid; i < DD; i += 256) sbv[i] = b_in[i];
    if (tid < 128) snq[tid] = 0.f;

    // ---- prefetch B buffers 0 and 1 (j256 x k64, pitch 128B) ----
#pragma unroll 1
    for (int h = 0; h < 2; h++) {
        const uint32_t bbuf = sbase + K8_B + (h & 1) * K8_BB;
        const int jc = h >> 3, kq = h & 7;
#pragma unroll
        for (int it = 0; it < 8; it++) {
            int idx = it * 256 + tid;
            int j = idx >> 3, ci = idx & 7;
            cp_async16(bbuf + j * 128 + ((ci ^ (j & 7)) << 4),
                       g_wbf + (size_t)(jc * 256 + j) * DD + kq * 64 + ci * 8);
        }
        cp_commit();
    }

    // ---- load A: read z fp32, convert to bf16 in-register, store swizzled --
#pragma unroll
    for (int it = 0; it < 32; it++) {
        int idx = it * 256 + tid;
        int r = idx >> 6, ci = idx & 63;          // ci = 16B chunk (8 bf16)
        int grow = m0 + r; if (grow > N - 1) grow = N - 1;
        const float4* zp = (const float4*)(z + (size_t)grow * DD + ci * 8);
        float4 v0 = zp[0];
        float4 v1 = zp[1];
        __nv_bfloat162 p0 = __floats2bfloat162_rn(v0.x, v0.y);
        __nv_bfloat162 p1 = __floats2bfloat162_rn(v0.z, v0.w);
        __nv_bfloat162 p2 = __floats2bfloat162_rn(v1.x, v1.y);
        __nv_bfloat162 p3 = __floats2bfloat162_rn(v1.z, v1.w);
        uint4 val;
        val.x = *reinterpret_cast<uint32_t*>(&p0);
        val.y = *reinterpret_cast<uint32_t*>(&p1);
        val.z = *reinterpret_cast<uint32_t*>(&p2);
        val.w = *reinterpret_cast<uint32_t*>(&p3);
        *(uint4*)(smem + K8_A + r * 1024 + ((ci ^ (r & 7)) << 4)) = val;
    }

    // ---- warp coords: mg = warp&1 (m64), jg = warp>>1 (j64 of j256) ----
    const int mg = warp & 1, jg = warp >> 1;
    const int mbase = mg * 64;
    const uint32_t swa = lane & 7;
    const uint32_t a0base = sbase + K8_A + (uint32_t)(mbase + (lane & 15)) * 1024;
    const int jrow = (lane & 7) + ((lane >> 4) << 3);
    const uint32_t brow_off = (uint32_t)(jg * 64 + jrow) * 128;
    const uint32_t ciBofs = (lane >> 3) & 1;
    const uint32_t ciAofs = lane >> 4;

    float acc[32][4];
#pragma unroll
    for (int t = 0; t < 32; t++)
#pragma unroll
        for (int e = 0; e < 4; e++) acc[t][e] = 0.f;
    float nsq[4][2] = {{0.f,0.f},{0.f,0.f},{0.f,0.f},{0.f,0.f}};

    for (int h = 0; h < 16; h++) {           // jc = h>>3 (j256), kq = h&7 (k64)
        const int buf = h & 1, jc = h >> 3, kq = h & 7;
        cp_wait1();
        __syncthreads();
        const uint32_t b0base = sbase + K8_B + buf * K8_BB + brow_off;

#pragma unroll
        for (int ktl = 0; ktl < 4; ktl++) {  // k16 steps within k64
            uint32_t a[4][4], bb[4][4];
            uint32_t ciA = (uint32_t)(kq * 4 + ktl) * 2 + ciAofs;
            uint32_t adr = a0base + ((ciA ^ swa) << 4);
            ldmx4(a[0], adr);
            ldmx4(a[1], adr + 16 * 1024);
            ldmx4(a[2], adr + 32 * 1024);
            ldmx4(a[3], adr + 48 * 1024);
            uint32_t ciB = (uint32_t)ktl * 2 + ciBofs;
            uint32_t bdr = b0base + ((ciB ^ swa) << 4);
            ldmx4(bb[0], bdr);
            ldmx4(bb[1], bdr + 16 * 128);
            ldmx4(bb[2], bdr + 32 * 128);
            ldmx4(bb[3], bdr + 48 * 128);
#pragma unroll
            for (int mt = 0; mt < 4; mt++) {
#pragma unroll
                for (int nt = 0; nt < 8; nt++)
                    mma16816(acc[mt * 8 + nt], a[mt], bb[nt >> 1] + (nt & 1) * 2);
            }
        }
        __syncthreads();   // all warps done with buf before refill

        if (kq == 7) {
            // j256 chunk complete over k512: fold (acc + b)^2, reset acc
#pragma unroll
            for (int mt = 0; mt < 4; mt++)
#pragma unroll
                for (int nt = 0; nt < 8; nt++) {
                    int jglob = jc * 256 + jg * 64 + nt * 8 + (lane & 3) * 2;
                    float bx = sbv[jglob], by = sbv[jglob + 1];
                    float* a = acc[mt * 8 + nt];
                    float v0 = a[0] + bx, v1 = a[1] + by;
                    float v2 = a[2] + bx, v3 = a[3] + by;
                    nsq[mt][0] += v0 * v0 + v1 * v1;
                    nsq[mt][1] += v2 * v2 + v3 * v3;
                    a[0] = 0.f; a[1] = 0.f; a[2] = 0.f; a[3] = 0.f;
                }
        }
        if (h + 2 < 16) {
            const int h2 = h + 2;
            const uint32_t bbuf = sbase + K8_B + buf * K8_BB;
            const int jc2 = h2 >> 3, kq2 = h2 & 7;
#pragma unroll
            for (int it = 0; it < 8; it++) {
                int idx = it * 256 + tid;
                int j = idx >> 3, ci = idx & 7;
                cp_async16(bbuf + j * 128 + ((ci ^ (j & 7)) << 4),
                           g_wbf + (size_t)(jc2 * 256 + j) * DD + kq2 * 64 + ci * 8);
            }
        }
        cp_commit();
    }

    // ---- merge lane partials: quad lanes share a row ----
#pragma unroll
    for (int mt = 0; mt < 4; mt++)
#pragma unroll
        for (int hh = 0; hh < 2; hh++) {
            float vn = nsq[mt][hh];
            vn += __shfl_xor_sync(0xffffffffu, vn, 1);
            vn += __shfl_xor_sync(0xffffffffu, vn, 2);
            if ((lane & 3) == 0)
                atomicAdd(&snq[mbase + mt * 16 + hh * 8 + (lane >> 2)], vn);
        }
    __syncthreads();

    if (tid < 128 && m0 + tid < N) g_nsq[m0 + tid] = snq[tid];
}

// ================= k10: finalize dist =================
__global__ void k10_final(float* __restrict__ out, int N) {
    int i = blockIdx.x * blockDim.x + threadIdx.x;
    if (i < N) {
        float nx = fmaxf(sqrtf(g_nsq[i]), EPS);
        out[i] = 1.0f - (g_dot[i] + g_bc) / (nx * g_cnorm);
    }
}

// ================= launch (forked graph; GEMM starts at t~0) ==============
extern "C" void kernel_launch(void* const* d_in, const int* in_sizes, int n_in,
                              void* d_out, int out_size) {
    const float* z = (const float*)d_in[0];
    const float* W = (const float*)d_in[1];
    const float* b = (const float*)d_in[2];
    float* out = (float*)d_out;
    const int N = in_sizes[0] / DD;

    cudaEventRecord(g_ev0, 0);
    cudaStreamWaitEvent(g_s1, g_ev0, 0);

    // side branch: W convert then the full norm-GEMM (independent of k1)
    k0b_wcvt<<<512, 256, 0, g_s1>>>(W);
    cudaFuncSetAttribute(k8_gemm, cudaFuncAttributeMaxDynamicSharedMemorySize, K8_SMEM);
    k8_gemm<<<(N + 127) / 128, 256, K8_SMEM, g_s1>>>(z, b, N);
    cudaEventRecord(g_ev1, g_s1);

    // main branch: centroid chain + exact numerator (overlaps with GEMM)
    k0a_zero<<<3, 256>>>();
    k1_pass1<<<1184, 256>>>(z, N);
    k2_c0<<<1, 512>>>(N);
    k3_d2<<<1184, 256>>>(N);
    k45_Zc<<<592, 256>>>(z, N);
    k7_norm<<<1, 512>>>(b);
    k6_v<<<32, 512>>>(W);
    k9_dot<<<1184, 256>>>(N);

    // join + finalize
    cudaStreamWaitEvent(0, g_ev1, 0);
    k10_final<<<(N + 255) / 256, 256>>>(out, N);
}